// round 15
// baseline (speedup 1.0000x reference)
#include <cuda_runtime.h>

#define BATCH 256
#define CHAN  512
#define SEQL  2048
#define HID   32
#define FLEN  8

// Scratch (no allocations allowed in kernel_launch)
__device__ float g_stat[BATCH * CHAN];
__device__ float g_loss[BATCH];
__device__ int   g_cnt[BATCH];   // zero at load; finisher resets each launch
__device__ int   g_done;         // zero at load; summing finisher resets

__device__ __forceinline__ void red_add_release_gpu(int* p, int v) {
    asm volatile("red.release.gpu.global.add.s32 [%0], %1;"
                 :: "l"(p), "r"(v) : "memory");
}
__device__ __forceinline__ int ld_acquire_gpu(const int* p) {
    int v;
    asm volatile("ld.acquire.gpu.global.s32 %0, [%1];"
                 : "=r"(v) : "l"(p) : "memory");
    return v;
}
__device__ __forceinline__ int atom_add_release_gpu(int* p, int v) {
    int old;
    asm volatile("atom.release.gpu.global.add.s32 %0, [%1], %2;"
                 : "=r"(old) : "l"(p), "r"(v) : "memory");
    return old;
}
__device__ __forceinline__ int atom_add_acquire_gpu(int* p, int v) {
    int old;
    asm volatile("atom.acquire.gpu.global.add.s32 %0, [%1], %2;"
                 : "=r"(old) : "l"(p), "r"(v) : "memory");
    return old;
}

// ---------------------------------------------------------------------------
// One launch, two roles:
//   blockIdx <  256          : finisher block for sample b = blockIdx.
//       Polls g_cnt[b] (acquire) until all 512 row-warps have published,
//       then runs the MLP tail. The 256th finished sample sums the loss.
//   blockIdx >= 256          : streaming block (8 rows, 1 per warp).
//       Pure R1-style max-reduce + __stcg publish + fire-and-forget
//       red.release per warp. NO barrier, NO atomic-result wait.
// ---------------------------------------------------------------------------
__global__ void __launch_bounds__(256, 8) fused_kernel(
    const float* __restrict__ x,
    const float* __restrict__ W1, const float* __restrict__ b1,
    const float* __restrict__ W2, const float* __restrict__ b2,
    const float* __restrict__ W3, const float* __restrict__ b3,
    float* __restrict__ out)
{
    const int tid  = threadIdx.x;
    const int warp = tid >> 5;          // 0..7
    const int lane = tid & 31;

    if (blockIdx.x >= BATCH) {
        // ==================== Streaming role ===============================
        const int sb      = blockIdx.x - BATCH;     // streaming block index
        const int row_idx = sb * 8 + warp;          // global (b,c) row
        const int b       = row_idx >> 9;           // sample (row / 512)

        const float4* row = reinterpret_cast<const float4*>(x)
                          + (size_t)row_idx * (SEQL / 4);
        float m = -3.402823466e38f;
#pragma unroll
        for (int i = 0; i < (SEQL / 4) / 32; ++i) {
            float4 v = __ldcs(row + i * 32 + lane);
            m = fmaxf(m, fmaxf(fmaxf(v.x, v.y), fmaxf(v.z, v.w)));
        }
#pragma unroll
        for (int off = 16; off; off >>= 1)
            m = fmaxf(m, __shfl_xor_sync(0xffffffffu, m, off));
        if (lane == 0) {
            __stcg(&g_stat[row_idx], m);      // publish via L2
            red_add_release_gpu(&g_cnt[b], 1); // no-return: zero added latency
        }
        return;
    }

    // ======================== Finisher role ================================
    const int b = blockIdx.x;   // sample owned by this finisher

    __shared__ float4 s_stat4[CHAN / 4];
    __shared__ float  s_h1[HID];
    __shared__ float  s_h2[HID];
    __shared__ float  s_f[2 * FLEN];

    // Wait until all 512 row-warps of sample b have published (acquire).
    if (tid == 0) {
        while (ld_acquire_gpu(&g_cnt[b]) != 512)
            __nanosleep(128);
        g_cnt[b] = 0;                          // reset for next graph replay
    }
    __syncthreads();

    // Gather stat row from L2
    if (tid < CHAN / 4) {
        const float4* srow = reinterpret_cast<const float4*>(g_stat + b * CHAN);
        s_stat4[tid] = __ldcg(srow + tid);
    }
    __syncthreads();

    // h1[h] = relu(dot(stat, W1[h,:]) + b1[h]); warp w owns h = 4w..4w+3
    {
        float p[4];
#pragma unroll
        for (int j = 0; j < 4; ++j) {
            const int h = warp * 4 + j;
            const float4* w4 = reinterpret_cast<const float4*>(W1 + h * CHAN);
            float acc = 0.0f;
#pragma unroll
            for (int i = 0; i < 4; ++i) {
                float4 wv = __ldg(w4 + i * 32 + lane);
                float4 sv = s_stat4[i * 32 + lane];
                acc = fmaf(wv.x, sv.x, acc);
                acc = fmaf(wv.y, sv.y, acc);
                acc = fmaf(wv.z, sv.z, acc);
                acc = fmaf(wv.w, sv.w, acc);
            }
            p[j] = acc;
        }
#pragma unroll
        for (int off = 16; off; off >>= 1) {
#pragma unroll
            for (int j = 0; j < 4; ++j)
                p[j] += __shfl_xor_sync(0xffffffffu, p[j], off);
        }
        if (lane < 4) {
            const int h = warp * 4 + lane;
            s_h1[h] = fmaxf(p[lane] + b1[h], 0.0f);
        }
    }
    __syncthreads();

    // ---- tiny layers + loss on warp 0 -------------------------------------
    if (warp != 0) return;
    const int t = lane;

    // h2 = relu(h1 @ W2^T + b2)
    {
        float acc = b2[t];
        const float* w = W2 + t * HID;
#pragma unroll
        for (int k = 0; k < HID; ++k)
            acc = fmaf(s_h1[k], __ldg(w + k), acc);
        s_h2[t] = fmaxf(acc, 0.0f);
    }
    __syncwarp();

    // filters = h2 @ W3^T + b3 (16 outputs)
    if (t < 2 * FLEN) {
        float acc = b3[t];
        const float* w = W3 + t * HID;
#pragma unroll
        for (int k = 0; k < HID; ++k)
            acc = fmaf(s_h2[k], __ldg(w + k), acc);
        s_f[t] = acc;
    }
    __syncwarp();

    // Outputs: out[0:2048] = lo, out[2048:4096] = hi
    if (t < FLEN) {
        out[b * FLEN + t]                = s_f[t];
        out[BATCH * FLEN + b * FLEN + t] = s_f[FLEN + t];
    }

    // Per-sample ortho loss (thread 0), filters read from smem
    if (t == 0) {
        float nl = 0.0f, nh = 0.0f;
#pragma unroll
        for (int f = 0; f < FLEN; ++f) {
            nl = fmaf(s_f[f], s_f[f], nl);
            nh = fmaf(s_f[FLEN + f], s_f[FLEN + f], nh);
        }
        const float inl = rsqrtf(nl);
        const float inh = rsqrtf(nh);

        float ps = 0.0f;
#pragma unroll
        for (int s = 1; s < FLEN; s += 2) {
            float dot = 0.0f;
#pragma unroll
            for (int f = 0; f < FLEN; ++f)
                dot = fmaf(s_f[f], s_f[(f - s) & (FLEN - 1)], dot);
            ps += fabsf(dot * inl * inl);
        }
        float dLH = 0.0f, dLL = 0.0f, dHH = 0.0f;
#pragma unroll
        for (int f = 0; f < FLEN; ++f) {
            dLH = fmaf(s_f[f], s_f[FLEN + f], dLH);
            dLL = fmaf(s_f[f], s_f[f], dLL);
            dHH = fmaf(s_f[FLEN + f], s_f[FLEN + f], dHH);
        }
        ps += fabsf(dLH * inl * inh)
            + fabsf(dLL * inl * inl - 1.0f)
            + fabsf(dHH * inh * inh - 1.0f);
        __stcg(&g_loss[b], ps);            // publish via L2
    }

    // ---- Elect final finisher; sum loss deterministically -----------------
    int done_old = 0;
    if (t == 0)
        done_old = atom_add_release_gpu(&g_done, 1);   // orders g_loss[b]
    done_old = __shfl_sync(0xffffffffu, done_old, 0);
    if (done_old == BATCH - 1) {
        if (t == 0) (void)atom_add_acquire_gpu(&g_done, 0);
        __syncwarp();
        // lane t loads g_loss[8t .. 8t+8) up-front (MLP=8), sums fixed order
        float v0 = __ldcg(g_loss + t * 8 + 0);
        float v1 = __ldcg(g_loss + t * 8 + 1);
        float v2 = __ldcg(g_loss + t * 8 + 2);
        float v3 = __ldcg(g_loss + t * 8 + 3);
        float v4 = __ldcg(g_loss + t * 8 + 4);
        float v5 = __ldcg(g_loss + t * 8 + 5);
        float v6 = __ldcg(g_loss + t * 8 + 6);
        float v7 = __ldcg(g_loss + t * 8 + 7);
        float v = ((((((v0 + v1) + v2) + v3) + v4) + v5) + v6) + v7;
#pragma unroll
        for (int off = 16; off; off >>= 1)
            v += __shfl_xor_sync(0xffffffffu, v, off);
        if (t == 0) {
            out[2 * BATCH * FLEN] = v / (float)BATCH;
            g_done = 0;                    // reset for next replay
        }
    }
}

// ---------------------------------------------------------------------------
extern "C" void kernel_launch(void* const* d_in, const int* in_sizes, int n_in,
                              void* d_out, int out_size) {
    const float* x  = (const float*)d_in[0];
    const float* W1 = (const float*)d_in[1];
    const float* b1 = (const float*)d_in[2];
    const float* W2 = (const float*)d_in[3];
    const float* b2 = (const float*)d_in[4];
    const float* W3 = (const float*)d_in[5];
    const float* b3 = (const float*)d_in[6];
    float* out = (float*)d_out;

    // 256 finisher blocks + 16384 streaming blocks (8 rows each)
    fused_kernel<<<BATCH + (BATCH * CHAN) / 8, 256>>>(x, W1, b1, W2, b2, W3, b3, out);
}

// round 16
// speedup vs baseline: 1.0204x; 1.0204x over previous
#include <cuda_runtime.h>

#define BATCH 256
#define CHAN  512
#define SEQL  2048
#define HID   32
#define FLEN  8

// Scratch (no allocations allowed in kernel_launch)
__device__ float g_stat[BATCH * CHAN];
__device__ float g_loss[BATCH];
__device__ int   g_cnt[BATCH];   // zero at load; tail resets each launch
__device__ int   g_done;         // zero at load; final tail resets

__device__ __forceinline__ void red_add_release_gpu(int* p, int v) {
    asm volatile("red.release.gpu.global.add.s32 [%0], %1;"
                 :: "l"(p), "r"(v) : "memory");
}
__device__ __forceinline__ int ld_acquire_gpu(const int* p) {
    int v;
    asm volatile("ld.acquire.gpu.global.s32 %0, [%1];"
                 : "=r"(v) : "l"(p) : "memory");
    return v;
}
__device__ __forceinline__ int atom_add_release_gpu(int* p, int v) {
    int old;
    asm volatile("atom.release.gpu.global.add.s32 %0, [%1], %2;"
                 : "=r"(old) : "l"(p), "r"(v) : "memory");
    return old;
}
__device__ __forceinline__ int atom_add_acquire_gpu(int* p, int v) {
    int old;
    asm volatile("atom.acquire.gpu.global.add.s32 %0, [%1], %2;"
                 : "=r"(old) : "l"(p), "r"(v) : "memory");
    return old;
}

// ---------------------------------------------------------------------------
// 16384 blocks x 256 threads; block covers 8 rows (1/warp) of sample
// b = blockIdx/64. Every warp publishes its row max (stcg) + fire-and-forget
// red.release increment, then EXITS — no __syncthreads, no atomic-result wait.
// The designated tail block ((blockIdx&63)==63) — launched alongside its
// sample's other blocks — briefly polls g_cnt[b]==512, then runs the MLP tail.
// ---------------------------------------------------------------------------
__global__ void __launch_bounds__(256, 8) fused_kernel(
    const float* __restrict__ x,
    const float* __restrict__ W1, const float* __restrict__ b1,
    const float* __restrict__ W2, const float* __restrict__ b2,
    const float* __restrict__ W3, const float* __restrict__ b3,
    float* __restrict__ out)
{
    const int tid  = threadIdx.x;
    const int warp = tid >> 5;          // 0..7
    const int lane = tid & 31;
    const int b    = blockIdx.x >> 6;   // sample
    const bool is_tail = (blockIdx.x & 63) == 63;

    // ---- Streaming: max over L for this block's 8 rows --------------------
    {
        const int row_idx = blockIdx.x * 8 + warp;       // global (b,c) row
        const float4* row = reinterpret_cast<const float4*>(x)
                          + (size_t)row_idx * (SEQL / 4);
        float m = -3.402823466e38f;
#pragma unroll
        for (int i = 0; i < (SEQL / 4) / 32; ++i) {
            float4 v = __ldcs(row + i * 32 + lane);
            m = fmaxf(m, fmaxf(fmaxf(v.x, v.y), fmaxf(v.z, v.w)));
        }
#pragma unroll
        for (int off = 16; off; off >>= 1)
            m = fmaxf(m, __shfl_xor_sync(0xffffffffu, m, off));
        if (lane == 0) {
            __stcg(&g_stat[row_idx], m);        // publish via L2
            red_add_release_gpu(&g_cnt[b], 1);  // no-return, zero wait
        }
    }
    if (!is_tail) return;   // streaming blocks exit immediately, per-warp

    // ======================= Tail: finish sample b =========================
    __shared__ float4 s_stat4[CHAN / 4];
    __shared__ float  s_h1[HID];
    __shared__ float  s_h2[HID];
    __shared__ float  s_f[2 * FLEN];

    __syncthreads();
    // Short poll: the other 63 blocks of this sample are contiguous bids and
    // already in flight.
    if (tid == 0) {
        while (ld_acquire_gpu(&g_cnt[b]) != 512)
            __nanosleep(64);
        g_cnt[b] = 0;                          // reset for next graph replay
    }
    __syncthreads();

    // Gather stat row from L2
    if (tid < CHAN / 4) {
        const float4* srow = reinterpret_cast<const float4*>(g_stat + b * CHAN);
        s_stat4[tid] = __ldcg(srow + tid);
    }
    __syncthreads();

    // h1[h] = relu(dot(stat, W1[h,:]) + b1[h]); warp w owns h = 4w..4w+3
    {
        float p[4];
#pragma unroll
        for (int j = 0; j < 4; ++j) {
            const int h = warp * 4 + j;
            const float4* w4 = reinterpret_cast<const float4*>(W1 + h * CHAN);
            float acc = 0.0f;
#pragma unroll
            for (int i = 0; i < 4; ++i) {
                float4 wv = __ldg(w4 + i * 32 + lane);
                float4 sv = s_stat4[i * 32 + lane];
                acc = fmaf(wv.x, sv.x, acc);
                acc = fmaf(wv.y, sv.y, acc);
                acc = fmaf(wv.z, sv.z, acc);
                acc = fmaf(wv.w, sv.w, acc);
            }
            p[j] = acc;
        }
#pragma unroll
        for (int off = 16; off; off >>= 1) {
#pragma unroll
            for (int j = 0; j < 4; ++j)
                p[j] += __shfl_xor_sync(0xffffffffu, p[j], off);
        }
        if (lane < 4) {
            const int h = warp * 4 + lane;
            s_h1[h] = fmaxf(p[lane] + b1[h], 0.0f);
        }
    }
    __syncthreads();

    // ---- tiny layers + loss on warp 0 -------------------------------------
    if (warp != 0) return;
    const int t = lane;

    // h2 = relu(h1 @ W2^T + b2)
    {
        float acc = b2[t];
        const float* w = W2 + t * HID;
#pragma unroll
        for (int k = 0; k < HID; ++k)
            acc = fmaf(s_h1[k], __ldg(w + k), acc);
        s_h2[t] = fmaxf(acc, 0.0f);
    }
    __syncwarp();

    // filters = h2 @ W3^T + b3 (16 outputs)
    if (t < 2 * FLEN) {
        float acc = b3[t];
        const float* w = W3 + t * HID;
#pragma unroll
        for (int k = 0; k < HID; ++k)
            acc = fmaf(s_h2[k], __ldg(w + k), acc);
        s_f[t] = acc;
    }
    __syncwarp();

    // Outputs: out[0:2048] = lo, out[2048:4096] = hi
    if (t < FLEN) {
        out[b * FLEN + t]                = s_f[t];
        out[BATCH * FLEN + b * FLEN + t] = s_f[FLEN + t];
    }

    // Per-sample ortho loss (thread 0), filters read from smem
    if (t == 0) {
        float nl = 0.0f, nh = 0.0f;
#pragma unroll
        for (int f = 0; f < FLEN; ++f) {
            nl = fmaf(s_f[f], s_f[f], nl);
            nh = fmaf(s_f[FLEN + f], s_f[FLEN + f], nh);
        }
        const float inl = rsqrtf(nl);
        const float inh = rsqrtf(nh);

        float ps = 0.0f;
#pragma unroll
        for (int s = 1; s < FLEN; s += 2) {
            float dot = 0.0f;
#pragma unroll
            for (int f = 0; f < FLEN; ++f)
                dot = fmaf(s_f[f], s_f[(f - s) & (FLEN - 1)], dot);
            ps += fabsf(dot * inl * inl);
        }
        float dLH = 0.0f, dLL = 0.0f, dHH = 0.0f;
#pragma unroll
        for (int f = 0; f < FLEN; ++f) {
            dLH = fmaf(s_f[f], s_f[FLEN + f], dLH);
            dLL = fmaf(s_f[f], s_f[f], dLL);
            dHH = fmaf(s_f[FLEN + f], s_f[FLEN + f], dHH);
        }
        ps += fabsf(dLH * inl * inh)
            + fabsf(dLL * inl * inl - 1.0f)
            + fabsf(dHH * inh * inh - 1.0f);
        __stcg(&g_loss[b], ps);            // publish via L2
    }

    // ---- Elect final tail; sum loss deterministically ---------------------
    int done_old = 0;
    if (t == 0)
        done_old = atom_add_release_gpu(&g_done, 1);   // orders g_loss[b]
    done_old = __shfl_sync(0xffffffffu, done_old, 0);
    if (done_old == BATCH - 1) {
        if (t == 0) (void)atom_add_acquire_gpu(&g_done, 0);
        __syncwarp();
        // lane t loads g_loss[8t .. 8t+8) up-front (MLP=8), sums fixed order
        float v0 = __ldcg(g_loss + t * 8 + 0);
        float v1 = __ldcg(g_loss + t * 8 + 1);
        float v2 = __ldcg(g_loss + t * 8 + 2);
        float v3 = __ldcg(g_loss + t * 8 + 3);
        float v4 = __ldcg(g_loss + t * 8 + 4);
        float v5 = __ldcg(g_loss + t * 8 + 5);
        float v6 = __ldcg(g_loss + t * 8 + 6);
        float v7 = __ldcg(g_loss + t * 8 + 7);
        float v = ((((((v0 + v1) + v2) + v3) + v4) + v5) + v6) + v7;
#pragma unroll
        for (int off = 16; off; off >>= 1)
            v += __shfl_xor_sync(0xffffffffu, v, off);
        if (t == 0) {
            out[2 * BATCH * FLEN] = v / (float)BATCH;
            g_done = 0;                    // reset for next replay
        }
    }
}

// ---------------------------------------------------------------------------
extern "C" void kernel_launch(void* const* d_in, const int* in_sizes, int n_in,
                              void* d_out, int out_size) {
    const float* x  = (const float*)d_in[0];
    const float* W1 = (const float*)d_in[1];
    const float* b1 = (const float*)d_in[2];
    const float* W2 = (const float*)d_in[3];
    const float* b2 = (const float*)d_in[4];
    const float* W3 = (const float*)d_in[5];
    const float* b3 = (const float*)d_in[6];
    float* out = (float*)d_out;

    // 256*512 = 131072 rows, 8 rows/block -> 16384 blocks
    fused_kernel<<<(BATCH * CHAN) / 8, 256>>>(x, W1, b1, W2, b2, W3, b3, out);
}

// round 17
// speedup vs baseline: 1.3453x; 1.3183x over previous
#include <cuda_runtime.h>

#define BATCH 256
#define CHAN  512
#define SEQL  2048
#define HID   32
#define FLEN  8

// Scratch (no allocations allowed in kernel_launch)
__device__ float g_stat[BATCH * CHAN];
__device__ float g_loss[BATCH];
__device__ int   g_cnt[BATCH];   // zero at load; tail block resets each launch
__device__ int   g_done;         // zero at load; final block resets each launch

__device__ __forceinline__ int atom_add_release_gpu(int* p, int v) {
    int old;
    asm volatile("atom.release.gpu.global.add.s32 %0, [%1], %2;"
                 : "=r"(old) : "l"(p), "r"(v) : "memory");
    return old;
}
__device__ __forceinline__ int atom_add_acquire_gpu(int* p, int v) {
    int old;
    asm volatile("atom.acquire.gpu.global.add.s32 %0, [%1], %2;"
                 : "=r"(old) : "l"(p), "r"(v) : "memory");
    return old;
}

// ---------------------------------------------------------------------------
// Fused kernel: 8192 blocks x 256 threads. Each block covers 16 rows of
// sample b = blockIdx/32 (2 rows per warp, independent max chains for 2x MLP).
// The 32nd block to publish (release atomic, R13-style) runs the MLP tail;
// the 256th sample-completion sums the loss deterministically.
// ---------------------------------------------------------------------------
__global__ void __launch_bounds__(256, 8) fused_kernel(
    const float* __restrict__ x,
    const float* __restrict__ W1, const float* __restrict__ b1,
    const float* __restrict__ W2, const float* __restrict__ b2,
    const float* __restrict__ W3, const float* __restrict__ b3,
    float* __restrict__ out)
{
    const int tid  = threadIdx.x;
    const int warp = tid >> 5;          // 0..7
    const int lane = tid & 31;
    const int b    = blockIdx.x >> 5;   // sample this block belongs to

    // ---- Phase 1: max over L for this block's 16 rows (2 per warp) --------
    {
        const int row0 = blockIdx.x * 16 + warp * 2;     // global (b,c) rows
        const float4* r0 = reinterpret_cast<const float4*>(x)
                         + (size_t)row0 * (SEQL / 4);
        const float4* r1 = r0 + (SEQL / 4);
        float m0 = -3.402823466e38f;
        float m1 = -3.402823466e38f;
#pragma unroll
        for (int i = 0; i < (SEQL / 4) / 32; ++i) {
            float4 a = __ldcs(r0 + i * 32 + lane);
            float4 c = __ldcs(r1 + i * 32 + lane);
            m0 = fmaxf(m0, fmaxf(fmaxf(a.x, a.y), fmaxf(a.z, a.w)));
            m1 = fmaxf(m1, fmaxf(fmaxf(c.x, c.y), fmaxf(c.z, c.w)));
        }
#pragma unroll
        for (int off = 16; off; off >>= 1) {
            m0 = fmaxf(m0, __shfl_xor_sync(0xffffffffu, m0, off));
            m1 = fmaxf(m1, __shfl_xor_sync(0xffffffffu, m1, off));
        }
        if (lane == 0) {
            __stcg(&g_stat[row0],     m0);   // straight to L2
            __stcg(&g_stat[row0 + 1], m1);
        }
    }
    __syncthreads();   // intra-block HB: all warps' stores precede tid0's atom

    // ---- Elect per-sample tail block (release atomic) ---------------------
    __shared__ int s_tail;
    if (tid == 0)
        s_tail = (atom_add_release_gpu(&g_cnt[b], 1) == 31);
    __syncthreads();
    if (!s_tail) return;

    // ======================= Tail: MLP for sample b ========================
    __shared__ float4 s_stat4[CHAN / 4];
    __shared__ float  s_h1[HID];
    __shared__ float  s_h2[HID];
    __shared__ float  s_f[2 * FLEN];

    if (tid == 0) {
        (void)atom_add_acquire_gpu(&g_cnt[b], 0);  // acquire: sync w/ 32 releases
        g_cnt[b] = 0;                              // reset for next replay
    }
    __syncthreads();

    // Load stat row from L2 (written via __stcg by other SMs)
    if (tid < CHAN / 4) {
        const float4* srow = reinterpret_cast<const float4*>(g_stat + b * CHAN);
        s_stat4[tid] = __ldcg(srow + tid);
    }
    __syncthreads();

    // h1[h] = relu(dot(stat, W1[h,:]) + b1[h]); warp w owns h = 4w..4w+3
    {
        float p[4];
#pragma unroll
        for (int j = 0; j < 4; ++j) {
            const int h = warp * 4 + j;
            const float4* w4 = reinterpret_cast<const float4*>(W1 + h * CHAN);
            float acc = 0.0f;
#pragma unroll
            for (int i = 0; i < 4; ++i) {
                float4 wv = __ldg(w4 + i * 32 + lane);
                float4 sv = s_stat4[i * 32 + lane];
                acc = fmaf(wv.x, sv.x, acc);
                acc = fmaf(wv.y, sv.y, acc);
                acc = fmaf(wv.z, sv.z, acc);
                acc = fmaf(wv.w, sv.w, acc);
            }
            p[j] = acc;
        }
#pragma unroll
        for (int off = 16; off; off >>= 1) {
#pragma unroll
            for (int j = 0; j < 4; ++j)
                p[j] += __shfl_xor_sync(0xffffffffu, p[j], off);
        }
        if (lane < 4) {
            const int h = warp * 4 + lane;
            s_h1[h] = fmaxf(p[lane] + b1[h], 0.0f);
        }
    }
    __syncthreads();

    // ---- tiny layers + loss on warp 0 -------------------------------------
    if (warp != 0) return;
    const int t = lane;

    // h2 = relu(h1 @ W2^T + b2)
    {
        float acc = b2[t];
        const float* w = W2 + t * HID;
#pragma unroll
        for (int k = 0; k < HID; ++k)
            acc = fmaf(s_h1[k], __ldg(w + k), acc);
        s_h2[t] = fmaxf(acc, 0.0f);
    }
    __syncwarp();

    // filters = h2 @ W3^T + b3 (16 outputs)
    if (t < 2 * FLEN) {
        float acc = b3[t];
        const float* w = W3 + t * HID;
#pragma unroll
        for (int k = 0; k < HID; ++k)
            acc = fmaf(s_h2[k], __ldg(w + k), acc);
        s_f[t] = acc;
    }
    __syncwarp();

    // Outputs: out[0:2048] = lo, out[2048:4096] = hi
    if (t < FLEN) {
        out[b * FLEN + t]                = s_f[t];
        out[BATCH * FLEN + b * FLEN + t] = s_f[FLEN + t];
    }

    // Per-sample ortho loss (thread 0), filters read from smem
    if (t == 0) {
        float nl = 0.0f, nh = 0.0f;
#pragma unroll
        for (int f = 0; f < FLEN; ++f) {
            nl = fmaf(s_f[f], s_f[f], nl);
            nh = fmaf(s_f[FLEN + f], s_f[FLEN + f], nh);
        }
        const float inl = rsqrtf(nl);
        const float inh = rsqrtf(nh);

        float ps = 0.0f;
#pragma unroll
        for (int s = 1; s < FLEN; s += 2) {
            float dot = 0.0f;
#pragma unroll
            for (int f = 0; f < FLEN; ++f)
                dot = fmaf(s_f[f], s_f[(f - s) & (FLEN - 1)], dot);
            ps += fabsf(dot * inl * inl);
        }
        float dLH = 0.0f, dLL = 0.0f, dHH = 0.0f;
#pragma unroll
        for (int f = 0; f < FLEN; ++f) {
            dLH = fmaf(s_f[f], s_f[FLEN + f], dLH);
            dLL = fmaf(s_f[f], s_f[f], dLL);
            dHH = fmaf(s_f[FLEN + f], s_f[FLEN + f], dHH);
        }
        ps += fabsf(dLH * inl * inh)
            + fabsf(dLL * inl * inl - 1.0f)
            + fabsf(dHH * inh * inh - 1.0f);
        __stcg(&g_loss[b], ps);            // publish via L2
    }

    // ---- Elect final block; sum loss deterministically ---------------------
    int done_old = 0;
    if (t == 0)
        done_old = atom_add_release_gpu(&g_done, 1);   // orders g_loss[b]
    done_old = __shfl_sync(0xffffffffu, done_old, 0);
    if (done_old == BATCH - 1) {
        if (t == 0) (void)atom_add_acquire_gpu(&g_done, 0);
        __syncwarp();
        // lane t loads g_loss[8t .. 8t+8) up-front (MLP=8), sums fixed order
        float v0 = __ldcg(g_loss + t * 8 + 0);
        float v1 = __ldcg(g_loss + t * 8 + 1);
        float v2 = __ldcg(g_loss + t * 8 + 2);
        float v3 = __ldcg(g_loss + t * 8 + 3);
        float v4 = __ldcg(g_loss + t * 8 + 4);
        float v5 = __ldcg(g_loss + t * 8 + 5);
        float v6 = __ldcg(g_loss + t * 8 + 6);
        float v7 = __ldcg(g_loss + t * 8 + 7);
        float v = ((((((v0 + v1) + v2) + v3) + v4) + v5) + v6) + v7;
#pragma unroll
        for (int off = 16; off; off >>= 1)
            v += __shfl_xor_sync(0xffffffffu, v, off);
        if (t == 0) {
            out[2 * BATCH * FLEN] = v / (float)BATCH;
            g_done = 0;                    // reset for next replay
        }
    }
}

// ---------------------------------------------------------------------------
extern "C" void kernel_launch(void* const* d_in, const int* in_sizes, int n_in,
                              void* d_out, int out_size) {
    const float* x  = (const float*)d_in[0];
    const float* W1 = (const float*)d_in[1];
    const float* b1 = (const float*)d_in[2];
    const float* W2 = (const float*)d_in[3];
    const float* b2 = (const float*)d_in[4];
    const float* W3 = (const float*)d_in[5];
    const float* b3 = (const float*)d_in[6];
    float* out = (float*)d_out;

    // 256*512 = 131072 rows, 16 rows/block -> 8192 blocks
    fused_kernel<<<(BATCH * CHAN) / 16, 256>>>(x, W1, b1, W2, b2, W3, b3, out);
}